// round 11
// baseline (speedup 1.0000x reference)
#include <cuda_runtime.h>
#include <cstdint>

#define M_SLOTS 10
#define HW      7744          // 88*88
#define HW4     1936          // HW in float4 units
#define ROWS    8192          // B*C
#define KC4     242           // chunk length in float4 units (1936/8)
#define NCH     8
#define RPB     8             // rows per block
#define NT      128           // 4 warps = 2 pairs; each pair shares 4 rows, splits j

typedef unsigned long long u64;

__device__ __forceinline__ u64 fma2(u64 a, u64 b, u64 c) {
    u64 d;
    asm("fma.rn.f32x2 %0, %1, %2, %3;" : "=l"(d) : "l"(a), "l"(b), "l"(c));
    return d;
}
__device__ __forceinline__ u64 pack2(float lo, float hi) {
    u64 t;
    asm("mov.b64 %0, {%1, %2};" : "=l"(t) : "f"(lo), "f"(hi));
    return t;
}
__device__ __forceinline__ void unpack2(u64 v, float& lo, float& hi) {
    asm("mov.b64 {%0, %1}, %2;" : "=f"(lo), "=f"(hi) : "l"(v));
}

__global__ __launch_bounds__(NT, 5)
void memaug_fused(const float* __restrict__ x,
                  const float* __restrict__ mem,
                  float* __restrict__ out) {
    __shared__ float4 w_s[M_SLOTS][KC4];        // 38,720 B chunk of mem
    __shared__ float  p_part[2][RPB][M_SLOTS];  // per-j-half partial dots
    __shared__ float  p_fin[RPB][M_SLOTS];      // probabilities

    const int tid   = threadIdx.x;
    const int lane  = tid & 31;
    const int warp  = tid >> 5;
    const int group = warp >> 1;     // 0,1 : which 4-row group
    const int half  = warp & 1;      // 0,1 : which half of the j range
    const int row0  = blockIdx.x * RPB + group * 4;

    const float4* __restrict__ m4 = (const float4*)mem;
    const float4* __restrict__ xr0 = (const float4*)(x + (size_t)(row0 + 0) * HW);
    const float4* __restrict__ xr1 = (const float4*)(x + (size_t)(row0 + 1) * HW);
    const float4* __restrict__ xr2 = (const float4*)(x + (size_t)(row0 + 2) * HW);
    const float4* __restrict__ xr3 = (const float4*)(x + (size_t)(row0 + 3) * HW);

    const int j0 = lane + 32 * half;    // start in [0,64), stride 64

    // ---------------- Phase 1: scores ----------------
    float acc[4][M_SLOTS];
    #pragma unroll
    for (int r = 0; r < 4; r++)
        #pragma unroll
        for (int m = 0; m < M_SLOTS; m++) acc[r][m] = 0.0f;

    for (int c = 0; c < NCH; c++) {
        for (int idx = tid; idx < M_SLOTS * KC4; idx += NT) {
            int m = idx / KC4;
            int j = idx - m * KC4;
            w_s[m][j] = __ldg(&m4[(size_t)m * HW4 + c * KC4 + j]);
        }
        __syncthreads();

        const int base = c * KC4;
        // 1-deep prefetch, stride 64
        int j = j0;
        float4 z = {0.f, 0.f, 0.f, 0.f};
        float4 a0 = z, a1 = z, a2 = z, a3 = z;
        a0 = __ldcs(xr0 + base + j); a1 = __ldcs(xr1 + base + j);
        a2 = __ldcs(xr2 + base + j); a3 = __ldcs(xr3 + base + j);
        while (j < KC4) {
            const int jn = j + 64;
            float4 b0 = z, b1 = z, b2 = z, b3 = z;
            if (jn < KC4) {
                b0 = __ldcs(xr0 + base + jn); b1 = __ldcs(xr1 + base + jn);
                b2 = __ldcs(xr2 + base + jn); b3 = __ldcs(xr3 + base + jn);
            }
            #pragma unroll
            for (int m = 0; m < M_SLOTS; m++) {
                float4 w = w_s[m][j];
                acc[0][m] = fmaf(a0.x, w.x, fmaf(a0.y, w.y, fmaf(a0.z, w.z, fmaf(a0.w, w.w, acc[0][m]))));
                acc[1][m] = fmaf(a1.x, w.x, fmaf(a1.y, w.y, fmaf(a1.z, w.z, fmaf(a1.w, w.w, acc[1][m]))));
                acc[2][m] = fmaf(a2.x, w.x, fmaf(a2.y, w.y, fmaf(a2.z, w.z, fmaf(a2.w, w.w, acc[2][m]))));
                acc[3][m] = fmaf(a3.x, w.x, fmaf(a3.y, w.y, fmaf(a3.z, w.z, fmaf(a3.w, w.w, acc[3][m]))));
            }
            a0 = b0; a1 = b1; a2 = b2; a3 = b3;
            j = jn;
        }
        __syncthreads();
    }

    // warp reduce -> p_part[half]
    #pragma unroll
    for (int r = 0; r < 4; r++) {
        #pragma unroll
        for (int m = 0; m < M_SLOTS; m++) {
            float v = acc[r][m];
            v += __shfl_xor_sync(0xFFFFFFFFu, v, 16);
            v += __shfl_xor_sync(0xFFFFFFFFu, v, 8);
            v += __shfl_xor_sync(0xFFFFFFFFu, v, 4);
            v += __shfl_xor_sync(0xFFFFFFFFu, v, 2);
            v += __shfl_xor_sync(0xFFFFFFFFu, v, 1);
            if (lane == 0) p_part[half][group * 4 + r][m] = v;
        }
    }
    __syncthreads();

    // softmax: one thread per row (sums the two j-halves)
    if (tid < RPB) {
        float s[M_SLOTS];
        float mx = -1e30f;
        #pragma unroll
        for (int m = 0; m < M_SLOTS; m++) {
            s[m] = p_part[0][tid][m] + p_part[1][tid][m];
            mx = fmaxf(mx, s[m]);
        }
        float sum = 0.0f;
        #pragma unroll
        for (int m = 0; m < M_SLOTS; m++) { s[m] = __expf(s[m] - mx); sum += s[m]; }
        float inv = 1.0f / sum;
        #pragma unroll
        for (int m = 0; m < M_SLOTS; m++) p_fin[tid][m] = s[m] * inv;
    }
    __syncthreads();

    // ---------------- Phase 2: value, row-pair packed f32x2 ---------------
    u64 p01[M_SLOTS], p23[M_SLOTS];
    #pragma unroll
    for (int m = 0; m < M_SLOTS; m++) {
        p01[m] = pack2(p_fin[group * 4 + 0][m], p_fin[group * 4 + 1][m]);
        p23[m] = pack2(p_fin[group * 4 + 2][m], p_fin[group * 4 + 3][m]);
    }

    float4* __restrict__ o0 = (float4*)(out + (size_t)(row0 + 0) * HW);
    float4* __restrict__ o1 = (float4*)(out + (size_t)(row0 + 1) * HW);
    float4* __restrict__ o2 = (float4*)(out + (size_t)(row0 + 2) * HW);
    float4* __restrict__ o3 = (float4*)(out + (size_t)(row0 + 3) * HW);

    for (int c = 0; c < NCH; c++) {
        for (int idx = tid; idx < M_SLOTS * KC4; idx += NT) {
            int m = idx / KC4;
            int j = idx - m * KC4;
            w_s[m][j] = __ldg(&m4[(size_t)m * HW4 + c * KC4 + j]);
        }
        __syncthreads();

        const int base = c * KC4;
        for (int j = j0; j < KC4; j += 64) {
            u64 a01x = 0ull, a01y = 0ull, a01z = 0ull, a01w = 0ull;
            u64 a23x = 0ull, a23y = 0ull, a23z = 0ull, a23w = 0ull;
            #pragma unroll
            for (int m = 0; m < M_SLOTS; m++) {
                float4 w = w_s[m][j];
                u64 wx = pack2(w.x, w.x);
                u64 wy = pack2(w.y, w.y);
                u64 wz = pack2(w.z, w.z);
                u64 ww = pack2(w.w, w.w);
                a01x = fma2(p01[m], wx, a01x);  a23x = fma2(p23[m], wx, a23x);
                a01y = fma2(p01[m], wy, a01y);  a23y = fma2(p23[m], wy, a23y);
                a01z = fma2(p01[m], wz, a01z);  a23z = fma2(p23[m], wz, a23z);
                a01w = fma2(p01[m], ww, a01w);  a23w = fma2(p23[m], ww, a23w);
            }
            float4 v0, v1, v2, v3;
            unpack2(a01x, v0.x, v1.x);  unpack2(a01y, v0.y, v1.y);
            unpack2(a01z, v0.z, v1.z);  unpack2(a01w, v0.w, v1.w);
            unpack2(a23x, v2.x, v3.x);  unpack2(a23y, v2.y, v3.y);
            unpack2(a23z, v2.z, v3.z);  unpack2(a23w, v2.w, v3.w);
            __stcs(o0 + base + j, v0);
            __stcs(o1 + base + j, v1);
            __stcs(o2 + base + j, v2);
            __stcs(o3 + base + j, v3);
        }
        __syncthreads();
    }
}

extern "C" void kernel_launch(void* const* d_in, const int* in_sizes, int n_in,
                              void* d_out, int out_size) {
    const float* x   = (const float*)d_in[0];   // [32,256,88,88]
    const float* mem = (const float*)d_in[1];   // [10,88,88]
    float* out = (float*)d_out;

    dim3 grid(ROWS / RPB);    // 1024 blocks
    memaug_fused<<<grid, NT>>>(x, mem, out);
}

// round 12
// speedup vs baseline: 1.2118x; 1.2118x over previous
#include <cuda_runtime.h>
#include <cstdint>

#define M_SLOTS 10
#define HW      7744          // 88*88
#define HW4     1936          // HW in float4 units
#define ROWS    8192          // B*C
#define QL      484           // j-quarter length in float4 units (1936/4)
#define RPB     4             // rows per block (shared by all 4 warps)
#define NT      128           // 4 warps, each owns one j-quarter of the 4 rows

typedef unsigned long long u64;

__device__ __forceinline__ u64 fma2(u64 a, u64 b, u64 c) {
    u64 d;
    asm("fma.rn.f32x2 %0, %1, %2, %3;" : "=l"(d) : "l"(a), "l"(b), "l"(c));
    return d;
}
__device__ __forceinline__ u64 pack2(float lo, float hi) {
    u64 t;
    asm("mov.b64 %0, {%1, %2};" : "=l"(t) : "f"(lo), "f"(hi));
    return t;
}
__device__ __forceinline__ void unpack2(u64 v, float& lo, float& hi) {
    asm("mov.b64 {%0, %1}, %2;" : "=f"(lo), "=f"(hi) : "l"(v));
}

__global__ __launch_bounds__(NT, 6)
void memaug_fused(const float* __restrict__ x,
                  const float* __restrict__ mem,
                  float* __restrict__ out) {
    __shared__ float p_part[4][RPB][M_SLOTS];   // per-quarter partial dots (640 B)
    __shared__ float p_fin[RPB][M_SLOTS];       // probabilities (160 B)

    const int tid  = threadIdx.x;
    const int lane = tid & 31;
    const int warp = tid >> 5;          // j-quarter index 0..3
    const int row0 = blockIdx.x * RPB;

    const float4* __restrict__ m4  = (const float4*)mem;
    const float4* __restrict__ xr0 = (const float4*)(x + (size_t)(row0 + 0) * HW);
    const float4* __restrict__ xr1 = (const float4*)(x + (size_t)(row0 + 1) * HW);
    const float4* __restrict__ xr2 = (const float4*)(x + (size_t)(row0 + 2) * HW);
    const float4* __restrict__ xr3 = (const float4*)(x + (size_t)(row0 + 3) * HW);

    const int jbeg = warp * QL + lane;
    const int jend = warp * QL + QL;

    // ---------------- Phase 1: partial scores over this warp's j-quarter ----
    float acc[4][M_SLOTS];
    #pragma unroll
    for (int r = 0; r < 4; r++)
        #pragma unroll
        for (int m = 0; m < M_SLOTS; m++) acc[r][m] = 0.0f;

    for (int j = jbeg; j < jend; j += 32) {
        float4 x0 = __ldcs(xr0 + j);
        float4 x1 = __ldcs(xr1 + j);
        float4 x2 = __ldcs(xr2 + j);
        float4 x3 = __ldcs(xr3 + j);
        #pragma unroll
        for (int m = 0; m < M_SLOTS; m++) {
            float4 w = __ldg(&m4[(size_t)m * HW4 + j]);
            acc[0][m] = fmaf(x0.x, w.x, fmaf(x0.y, w.y, fmaf(x0.z, w.z, fmaf(x0.w, w.w, acc[0][m]))));
            acc[1][m] = fmaf(x1.x, w.x, fmaf(x1.y, w.y, fmaf(x1.z, w.z, fmaf(x1.w, w.w, acc[1][m]))));
            acc[2][m] = fmaf(x2.x, w.x, fmaf(x2.y, w.y, fmaf(x2.z, w.z, fmaf(x2.w, w.w, acc[2][m]))));
            acc[3][m] = fmaf(x3.x, w.x, fmaf(x3.y, w.y, fmaf(x3.z, w.z, fmaf(x3.w, w.w, acc[3][m]))));
        }
    }

    // warp reduce -> p_part[warp]
    #pragma unroll
    for (int r = 0; r < 4; r++) {
        #pragma unroll
        for (int m = 0; m < M_SLOTS; m++) {
            float v = acc[r][m];
            v += __shfl_xor_sync(0xFFFFFFFFu, v, 16);
            v += __shfl_xor_sync(0xFFFFFFFFu, v, 8);
            v += __shfl_xor_sync(0xFFFFFFFFu, v, 4);
            v += __shfl_xor_sync(0xFFFFFFFFu, v, 2);
            v += __shfl_xor_sync(0xFFFFFFFFu, v, 1);
            if (lane == 0) p_part[warp][r][m] = v;
        }
    }
    __syncthreads();

    // softmax: one thread per row (sums the 4 quarters)
    if (tid < RPB) {
        float s[M_SLOTS];
        float mx = -1e30f;
        #pragma unroll
        for (int m = 0; m < M_SLOTS; m++) {
            s[m] = p_part[0][tid][m] + p_part[1][tid][m]
                 + p_part[2][tid][m] + p_part[3][tid][m];
            mx = fmaxf(mx, s[m]);
        }
        float sum = 0.0f;
        #pragma unroll
        for (int m = 0; m < M_SLOTS; m++) { s[m] = __expf(s[m] - mx); sum += s[m]; }
        float inv = 1.0f / sum;
        #pragma unroll
        for (int m = 0; m < M_SLOTS; m++) p_fin[tid][m] = s[m] * inv;
    }
    __syncthreads();

    // ---------------- Phase 2: value, row-pair packed f32x2 -----------------
    u64 p01[M_SLOTS], p23[M_SLOTS];
    #pragma unroll
    for (int m = 0; m < M_SLOTS; m++) {
        p01[m] = pack2(p_fin[0][m], p_fin[1][m]);
        p23[m] = pack2(p_fin[2][m], p_fin[3][m]);
    }

    float4* __restrict__ o0 = (float4*)(out + (size_t)(row0 + 0) * HW);
    float4* __restrict__ o1 = (float4*)(out + (size_t)(row0 + 1) * HW);
    float4* __restrict__ o2 = (float4*)(out + (size_t)(row0 + 2) * HW);
    float4* __restrict__ o3 = (float4*)(out + (size_t)(row0 + 3) * HW);

    for (int j = jbeg; j < jend; j += 32) {
        u64 a01x = 0ull, a01y = 0ull, a01z = 0ull, a01w = 0ull;
        u64 a23x = 0ull, a23y = 0ull, a23z = 0ull, a23w = 0ull;
        #pragma unroll
        for (int m = 0; m < M_SLOTS; m++) {
            float4 w = __ldg(&m4[(size_t)m * HW4 + j]);
            u64 wx = pack2(w.x, w.x);
            u64 wy = pack2(w.y, w.y);
            u64 wz = pack2(w.z, w.z);
            u64 ww = pack2(w.w, w.w);
            a01x = fma2(p01[m], wx, a01x);  a23x = fma2(p23[m], wx, a23x);
            a01y = fma2(p01[m], wy, a01y);  a23y = fma2(p23[m], wy, a23y);
            a01z = fma2(p01[m], wz, a01z);  a23z = fma2(p23[m], wz, a23z);
            a01w = fma2(p01[m], ww, a01w);  a23w = fma2(p23[m], ww, a23w);
        }
        float4 v0, v1, v2, v3;
        unpack2(a01x, v0.x, v1.x);  unpack2(a01y, v0.y, v1.y);
        unpack2(a01z, v0.z, v1.z);  unpack2(a01w, v0.w, v1.w);
        unpack2(a23x, v2.x, v3.x);  unpack2(a23y, v2.y, v3.y);
        unpack2(a23z, v2.z, v3.z);  unpack2(a23w, v2.w, v3.w);
        __stcs(o0 + j, v0);
        __stcs(o1 + j, v1);
        __stcs(o2 + j, v2);
        __stcs(o3 + j, v3);
    }
}

extern "C" void kernel_launch(void* const* d_in, const int* in_sizes, int n_in,
                              void* d_out, int out_size) {
    const float* x   = (const float*)d_in[0];   // [32,256,88,88]
    const float* mem = (const float*)d_in[1];   // [10,88,88]
    float* out = (float*)d_out;

    dim3 grid(ROWS / RPB);    // 2048 blocks
    memaug_fused<<<grid, NT>>>(x, mem, out);
}

// round 13
// speedup vs baseline: 1.2801x; 1.0563x over previous
#include <cuda_runtime.h>
#include <cstdint>

#define M_SLOTS 10
#define HW      7744          // 88*88
#define HW4     1936          // HW in float4 units
#define ROWS    8192          // B*C
#define QL      484           // j-quarter length in float4 units (1936/4)
#define RPB     4             // rows per block (shared by all 4 warps)
#define NT      128           // 4 warps, each owns one j-quarter of the 4 rows

typedef unsigned long long u64;

__device__ __forceinline__ u64 fma2(u64 a, u64 b, u64 c) {
    u64 d;
    asm("fma.rn.f32x2 %0, %1, %2, %3;" : "=l"(d) : "l"(a), "l"(b), "l"(c));
    return d;
}
__device__ __forceinline__ u64 pack2(float lo, float hi) {
    u64 t;
    asm("mov.b64 %0, {%1, %2};" : "=l"(t) : "f"(lo), "f"(hi));
    return t;
}
__device__ __forceinline__ void unpack2(u64 v, float& lo, float& hi) {
    asm("mov.b64 {%0, %1}, %2;" : "=f"(lo), "=f"(hi) : "l"(v));
}

__global__ __launch_bounds__(NT, 5)
void memaug_fused(const float* __restrict__ x,
                  const float* __restrict__ mem,
                  float* __restrict__ out) {
    __shared__ float p_part[4][RPB][M_SLOTS];   // per-quarter partial dots
    __shared__ float p_fin[RPB][M_SLOTS];       // probabilities

    const int tid  = threadIdx.x;
    const int lane = tid & 31;
    const int warp = tid >> 5;          // j-quarter index 0..3
    const int row0 = blockIdx.x * RPB;

    const float4* __restrict__ m4  = (const float4*)mem;
    const float4* __restrict__ xr0 = (const float4*)(x + (size_t)(row0 + 0) * HW);
    const float4* __restrict__ xr1 = (const float4*)(x + (size_t)(row0 + 1) * HW);
    const float4* __restrict__ xr2 = (const float4*)(x + (size_t)(row0 + 2) * HW);
    const float4* __restrict__ xr3 = (const float4*)(x + (size_t)(row0 + 3) * HW);

    const int jbeg = warp * QL + lane;
    const int jend = warp * QL + QL;

    // ---------------- Phase 1: packed f32x2 partial scores -----------------
    // a01[m] accumulates (dot_row0, dot_row1); a23[m] accumulates (dot_row2, dot_row3)
    u64 a01[M_SLOTS], a23[M_SLOTS];
    #pragma unroll
    for (int m = 0; m < M_SLOTS; m++) { a01[m] = 0ull; a23[m] = 0ull; }

    const float4 z4 = {0.f, 0.f, 0.f, 0.f};
    int j = jbeg;
    float4 xa0 = z4, xa1 = z4, xa2 = z4, xa3 = z4;
    if (j < jend) {
        xa0 = __ldcs(xr0 + j); xa1 = __ldcs(xr1 + j);
        xa2 = __ldcs(xr2 + j); xa3 = __ldcs(xr3 + j);
    }
    while (j < jend) {
        const int jn = j + 32;
        float4 xb0 = z4, xb1 = z4, xb2 = z4, xb3 = z4;
        if (jn < jend) {
            xb0 = __ldcs(xr0 + jn); xb1 = __ldcs(xr1 + jn);
            xb2 = __ldcs(xr2 + jn); xb3 = __ldcs(xr3 + jn);
        }
        // pack current x into row pairs
        u64 p01x = pack2(xa0.x, xa1.x), p01y = pack2(xa0.y, xa1.y);
        u64 p01z = pack2(xa0.z, xa1.z), p01w = pack2(xa0.w, xa1.w);
        u64 p23x = pack2(xa2.x, xa3.x), p23y = pack2(xa2.y, xa3.y);
        u64 p23z = pack2(xa2.z, xa3.z), p23w = pack2(xa2.w, xa3.w);
        #pragma unroll
        for (int m = 0; m < M_SLOTS; m++) {
            float4 w = __ldg(&m4[(size_t)m * HW4 + j]);
            u64 wx = pack2(w.x, w.x);
            u64 wy = pack2(w.y, w.y);
            u64 wz = pack2(w.z, w.z);
            u64 ww = pack2(w.w, w.w);
            a01[m] = fma2(p01x, wx, a01[m]);  a23[m] = fma2(p23x, wx, a23[m]);
            a01[m] = fma2(p01y, wy, a01[m]);  a23[m] = fma2(p23y, wy, a23[m]);
            a01[m] = fma2(p01z, wz, a01[m]);  a23[m] = fma2(p23z, wz, a23[m]);
            a01[m] = fma2(p01w, ww, a01[m]);  a23[m] = fma2(p23w, ww, a23[m]);
        }
        xa0 = xb0; xa1 = xb1; xa2 = xb2; xa3 = xb3;
        j = jn;
    }

    // warp reduce the packed partials -> p_part[warp]
    #pragma unroll
    for (int m = 0; m < M_SLOTS; m++) {
        float d0, d1, d2, d3;
        unpack2(a01[m], d0, d1);
        unpack2(a23[m], d2, d3);
        #pragma unroll
        for (int k = 16; k > 0; k >>= 1) {
            d0 += __shfl_xor_sync(0xFFFFFFFFu, d0, k);
            d1 += __shfl_xor_sync(0xFFFFFFFFu, d1, k);
            d2 += __shfl_xor_sync(0xFFFFFFFFu, d2, k);
            d3 += __shfl_xor_sync(0xFFFFFFFFu, d3, k);
        }
        if (lane == 0) {
            p_part[warp][0][m] = d0;
            p_part[warp][1][m] = d1;
            p_part[warp][2][m] = d2;
            p_part[warp][3][m] = d3;
        }
    }
    __syncthreads();

    // softmax: one thread per row (sums the 4 quarters)
    if (tid < RPB) {
        float s[M_SLOTS];
        float mx = -1e30f;
        #pragma unroll
        for (int m = 0; m < M_SLOTS; m++) {
            s[m] = p_part[0][tid][m] + p_part[1][tid][m]
                 + p_part[2][tid][m] + p_part[3][tid][m];
            mx = fmaxf(mx, s[m]);
        }
        float sum = 0.0f;
        #pragma unroll
        for (int m = 0; m < M_SLOTS; m++) { s[m] = __expf(s[m] - mx); sum += s[m]; }
        float inv = 1.0f / sum;
        #pragma unroll
        for (int m = 0; m < M_SLOTS; m++) p_fin[tid][m] = s[m] * inv;
    }
    __syncthreads();

    // ---------------- Phase 2: value, row-pair packed f32x2 -----------------
    u64 q01[M_SLOTS], q23[M_SLOTS];
    #pragma unroll
    for (int m = 0; m < M_SLOTS; m++) {
        q01[m] = pack2(p_fin[0][m], p_fin[1][m]);
        q23[m] = pack2(p_fin[2][m], p_fin[3][m]);
    }

    float4* __restrict__ o0 = (float4*)(out + (size_t)(row0 + 0) * HW);
    float4* __restrict__ o1 = (float4*)(out + (size_t)(row0 + 1) * HW);
    float4* __restrict__ o2 = (float4*)(out + (size_t)(row0 + 2) * HW);
    float4* __restrict__ o3 = (float4*)(out + (size_t)(row0 + 3) * HW);

    for (int jj = jbeg; jj < jend; jj += 32) {
        u64 a01x = 0ull, a01y = 0ull, a01z = 0ull, a01w = 0ull;
        u64 a23x = 0ull, a23y = 0ull, a23z = 0ull, a23w = 0ull;
        #pragma unroll
        for (int m = 0; m < M_SLOTS; m++) {
            float4 w = __ldg(&m4[(size_t)m * HW4 + jj]);
            u64 wx = pack2(w.x, w.x);
            u64 wy = pack2(w.y, w.y);
            u64 wz = pack2(w.z, w.z);
            u64 ww = pack2(w.w, w.w);
            a01x = fma2(q01[m], wx, a01x);  a23x = fma2(q23[m], wx, a23x);
            a01y = fma2(q01[m], wy, a01y);  a23y = fma2(q23[m], wy, a23y);
            a01z = fma2(q01[m], wz, a01z);  a23z = fma2(q23[m], wz, a23z);
            a01w = fma2(q01[m], ww, a01w);  a23w = fma2(q23[m], ww, a23w);
        }
        float4 v0, v1, v2, v3;
        unpack2(a01x, v0.x, v1.x);  unpack2(a01y, v0.y, v1.y);
        unpack2(a01z, v0.z, v1.z);  unpack2(a01w, v0.w, v1.w);
        unpack2(a23x, v2.x, v3.x);  unpack2(a23y, v2.y, v3.y);
        unpack2(a23z, v2.z, v3.z);  unpack2(a23w, v2.w, v3.w);
        __stcs(o0 + jj, v0);
        __stcs(o1 + jj, v1);
        __stcs(o2 + jj, v2);
        __stcs(o3 + jj, v3);
    }
}

extern "C" void kernel_launch(void* const* d_in, const int* in_sizes, int n_in,
                              void* d_out, int out_size) {
    const float* x   = (const float*)d_in[0];   // [32,256,88,88]
    const float* mem = (const float*)d_in[1];   // [10,88,88]
    float* out = (float*)d_out;

    dim3 grid(ROWS / RPB);    // 2048 blocks
    memaug_fused<<<grid, NT>>>(x, mem, out);
}

// round 14
// speedup vs baseline: 1.3369x; 1.0443x over previous
#include <cuda_runtime.h>
#include <cstdint>

#define M_SLOTS 10
#define HW      7744          // 88*88
#define HW2     484           // HW in 16B (double2/float4) units ... per quarter
#define HWV     1936          // HW in 16B units
#define ROWS    8192          // B*C
#define QL      484           // j-quarter length in 16B units (1936/4)
#define RPB     4             // rows per block (shared by all 4 warps)
#define NT      128           // 4 warps, each owns one j-quarter of the 4 rows

typedef unsigned long long u64;

__device__ __forceinline__ u64 fma2(u64 a, u64 b, u64 c) {
    u64 d;
    asm("fma.rn.f32x2 %0, %1, %2, %3;" : "=l"(d) : "l"(a), "l"(b), "l"(c));
    return d;
}
__device__ __forceinline__ u64 pack2(float lo, float hi) {
    u64 t;
    asm("mov.b64 %0, {%1, %2};" : "=l"(t) : "f"(lo), "f"(hi));
    return t;
}
__device__ __forceinline__ float hsum2(u64 a) {
    float x, y;
    asm("mov.b64 {%0, %1}, %2;" : "=f"(x), "=f"(y) : "l"(a));
    return x + y;
}
__device__ __forceinline__ u64 d2u(double d) { return (u64)__double_as_longlong(d); }
__device__ __forceinline__ double u2d(u64 v) { return __longlong_as_double((long long)v); }

__global__ __launch_bounds__(NT, 3)
void memaug_fused(const float* __restrict__ x,
                  const float* __restrict__ mem,
                  float* __restrict__ out) {
    __shared__ float p_part[4][RPB][M_SLOTS];   // per-quarter partial dots
    __shared__ float p_fin[RPB][M_SLOTS];       // probabilities

    const int tid  = threadIdx.x;
    const int lane = tid & 31;
    const int warp = tid >> 5;          // j-quarter index 0..3
    const int row0 = blockIdx.x * RPB;

    const double2* __restrict__ mw  = (const double2*)mem;
    const double2* __restrict__ xr0 = (const double2*)(x + (size_t)(row0 + 0) * HW);
    const double2* __restrict__ xr1 = (const double2*)(x + (size_t)(row0 + 1) * HW);
    const double2* __restrict__ xr2 = (const double2*)(x + (size_t)(row0 + 2) * HW);
    const double2* __restrict__ xr3 = (const double2*)(x + (size_t)(row0 + 3) * HW);

    const int jbeg = warp * QL + lane;
    const int jend = warp * QL + QL;

    // ------------- Phase 1: HW-dim packed f32x2 partial scores -------------
    // acc[r][m] holds a packed pair of partial sums over the HW dimension.
    u64 acc[RPB][M_SLOTS];
    #pragma unroll
    for (int r = 0; r < RPB; r++)
        #pragma unroll
        for (int m = 0; m < M_SLOTS; m++) acc[r][m] = 0ull;

    for (int j = jbeg; j < jend; j += 32) {
        double2 xd0 = __ldcs(xr0 + j);
        double2 xd1 = __ldcs(xr1 + j);
        double2 xd2 = __ldcs(xr2 + j);
        double2 xd3 = __ldcs(xr3 + j);
        const u64 x0a = d2u(xd0.x), x0b = d2u(xd0.y);
        const u64 x1a = d2u(xd1.x), x1b = d2u(xd1.y);
        const u64 x2a = d2u(xd2.x), x2b = d2u(xd2.y);
        const u64 x3a = d2u(xd3.x), x3b = d2u(xd3.y);
        #pragma unroll
        for (int m = 0; m < M_SLOTS; m++) {
            double2 wd = __ldg(&mw[(size_t)m * HWV + j]);
            const u64 wa = d2u(wd.x), wb = d2u(wd.y);
            acc[0][m] = fma2(x0a, wa, acc[0][m]);
            acc[1][m] = fma2(x1a, wa, acc[1][m]);
            acc[2][m] = fma2(x2a, wa, acc[2][m]);
            acc[3][m] = fma2(x3a, wa, acc[3][m]);
            acc[0][m] = fma2(x0b, wb, acc[0][m]);
            acc[1][m] = fma2(x1b, wb, acc[1][m]);
            acc[2][m] = fma2(x2b, wb, acc[2][m]);
            acc[3][m] = fma2(x3b, wb, acc[3][m]);
        }
    }

    // reduce packed pairs + warp tree -> p_part[warp]
    #pragma unroll
    for (int r = 0; r < RPB; r++) {
        #pragma unroll
        for (int m = 0; m < M_SLOTS; m++) {
            float v = hsum2(acc[r][m]);
            #pragma unroll
            for (int k = 16; k > 0; k >>= 1)
                v += __shfl_xor_sync(0xFFFFFFFFu, v, k);
            if (lane == 0) p_part[warp][r][m] = v;
        }
    }
    __syncthreads();

    // softmax: one thread per row (sums the 4 quarters)
    if (tid < RPB) {
        float s[M_SLOTS];
        float mx = -1e30f;
        #pragma unroll
        for (int m = 0; m < M_SLOTS; m++) {
            s[m] = p_part[0][tid][m] + p_part[1][tid][m]
                 + p_part[2][tid][m] + p_part[3][tid][m];
            mx = fmaxf(mx, s[m]);
        }
        float sum = 0.0f;
        #pragma unroll
        for (int m = 0; m < M_SLOTS; m++) { s[m] = __expf(s[m] - mx); sum += s[m]; }
        float inv = 1.0f / sum;
        #pragma unroll
        for (int m = 0; m < M_SLOTS; m++) p_fin[tid][m] = s[m] * inv;
    }
    __syncthreads();

    // ------------- Phase 2: value, HW-dim packed f32x2 ---------------------
    // q[r][m] = (p, p) packed once; acc pairs over HW dim; zero per-iter ALU.
    u64 q[RPB][M_SLOTS];
    #pragma unroll
    for (int r = 0; r < RPB; r++)
        #pragma unroll
        for (int m = 0; m < M_SLOTS; m++) {
            float pv = p_fin[r][m];
            q[r][m] = pack2(pv, pv);
        }

    double2* __restrict__ o0 = (double2*)(out + (size_t)(row0 + 0) * HW);
    double2* __restrict__ o1 = (double2*)(out + (size_t)(row0 + 1) * HW);
    double2* __restrict__ o2 = (double2*)(out + (size_t)(row0 + 2) * HW);
    double2* __restrict__ o3 = (double2*)(out + (size_t)(row0 + 3) * HW);

    for (int j = jbeg; j < jend; j += 32) {
        u64 a0a = 0ull, a0b = 0ull, a1a = 0ull, a1b = 0ull;
        u64 a2a = 0ull, a2b = 0ull, a3a = 0ull, a3b = 0ull;
        #pragma unroll
        for (int m = 0; m < M_SLOTS; m++) {
            double2 wd = __ldg(&mw[(size_t)m * HWV + j]);
            const u64 wa = d2u(wd.x), wb = d2u(wd.y);
            a0a = fma2(q[0][m], wa, a0a);  a0b = fma2(q[0][m], wb, a0b);
            a1a = fma2(q[1][m], wa, a1a);  a1b = fma2(q[1][m], wb, a1b);
            a2a = fma2(q[2][m], wa, a2a);  a2b = fma2(q[2][m], wb, a2b);
            a3a = fma2(q[3][m], wa, a3a);  a3b = fma2(q[3][m], wb, a3b);
        }
        double2 v0, v1, v2, v3;
        v0.x = u2d(a0a); v0.y = u2d(a0b);
        v1.x = u2d(a1a); v1.y = u2d(a1b);
        v2.x = u2d(a2a); v2.y = u2d(a2b);
        v3.x = u2d(a3a); v3.y = u2d(a3b);
        __stcs(o0 + j, v0);
        __stcs(o1 + j, v1);
        __stcs(o2 + j, v2);
        __stcs(o3 + j, v3);
    }
}

extern "C" void kernel_launch(void* const* d_in, const int* in_sizes, int n_in,
                              void* d_out, int out_size) {
    const float* x   = (const float*)d_in[0];   // [32,256,88,88]
    const float* mem = (const float*)d_in[1];   // [10,88,88]
    float* out = (float*)d_out;

    dim3 grid(ROWS / RPB);    // 2048 blocks
    memaug_fused<<<grid, NT>>>(x, mem, out);
}